// round 2
// baseline (speedup 1.0000x reference)
#include <cuda_runtime.h>
#include <cuda_bf16.h>

// Problem constants (fixed by reference setup_inputs):
//   b=4, u=9, v=9 (MD=4, FAC=1), h=256, w=448, WSIZE=3
#define MD    4
#define U_DIM 9
#define V_DIM 9
#define UV    81
#define WS    3
#define B_DIM 4

// 1/log(49), 1/log(81) (compile-time folded)
#define INV_L49 ((float)(1.0 / 3.8918202981106265))
#define INV_L81 ((float)(1.0 / 4.3944491546724391))

__global__ __launch_bounds__(256) void flow_reg_kernel(
    const float* __restrict__ x,   // (B, U, V, H, W)
    float* __restrict__ out,       // flow (B,2,H,W) followed by ent (B,2,H,W)
    int bhw, int hw)
{
    int t = blockIdx.x * blockDim.x + threadIdx.x;
    if (t >= bhw) return;
    int b = t / hw;
    int p = t - b * hw;

    const float* xp = x + (size_t)b * UV * hw + p;

    // ---- load the 81-deep displacement column into registers (coalesced per plane) ----
    float xv[UV];
#pragma unroll
    for (int k = 0; k < UV; ++k)
        xv[k] = __ldg(xp + (size_t)k * hw);

    // ---- argmax (first occurrence, matches jnp.argmax) ----
    float m = xv[0];
    int am = 0;
#pragma unroll
    for (int k = 1; k < UV; ++k) {
        if (xv[k] > m) { m = xv[k]; am = k; }
    }
    int iu = am / V_DIM;
    int iv = am - iu * V_DIM;

    // ---- single fused pass: global softmax stats + masked softmax stats ----
    // global:  Z = sum e^(x-m),           S  = sum (x-m) e^(x-m)
    // masked:  Zl, Sl over |u-iu|<=3 && |v-iv|<=3, plus flow moments Fx, Fy
    // (masked max == global max since the argmax element is inside the mask,
    //  so one exp per element serves both softmaxes)
    float Z = 0.f, S = 0.f, Zl = 0.f, Sl = 0.f, Fx = 0.f, Fy = 0.f;
#pragma unroll
    for (int k = 0; k < UV; ++k) {
        const int u = k / V_DIM;          // compile-time per unrolled k
        const int v = k - u * V_DIM;
        float d = xv[k] - m;
        float e = __expf(d);
        Z += e;
        S = fmaf(d, e, S);
        bool in = ((unsigned)(u - iu + WS) <= 2u * WS) &&
                  ((unsigned)(v - iv + WS) <= 2u * WS);
        float em = in ? e : 0.0f;
        Zl += em;
        Sl = fmaf(d, em, Sl);
        Fx = fmaf((float)(u - MD), em, Fx);
        Fy = fmaf((float)(v - MD), em, Fy);
    }

    float rZl = 1.0f / Zl;
    float rZ  = 1.0f / Z;
    float outx = Fx * rZl;
    float outy = Fy * rZl;
    // entropy = log Z - S/Z   (exact; reference's 1e-9 eps-clip is numerically negligible)
    float lent = (__logf(Zl) - Sl * rZl) * INV_L49;
    float gent = (__logf(Z)  - S  * rZ ) * INV_L81;

    // ---- write: flow block (B,2,H,W) then ent block (B,2,H,W) ----
    float* fo = out + (size_t)b * 2 * hw + p;
    fo[0]  = outx;
    fo[hw] = outy;
    float* eo = fo + (size_t)B_DIM * 2 * hw;
    eo[0]  = lent;
    eo[hw] = gent;
}

extern "C" void kernel_launch(void* const* d_in, const int* in_sizes, int n_in,
                              void* d_out, int out_size)
{
    const float* x = (const float*)d_in[0];
    float* out = (float*)d_out;

    // in_sizes[0] = B*U*V*H*W ; out_size = B*4*H*W
    int hw  = in_sizes[0] / (UV * B_DIM);   // H*W = 114688
    int bhw = B_DIM * hw;                   // 458752

    int threads = 256;
    int blocks = (bhw + threads - 1) / threads;
    flow_reg_kernel<<<blocks, threads>>>(x, out, bhw, hw);
}

// round 3
// speedup vs baseline: 1.0922x; 1.0922x over previous
#include <cuda_runtime.h>
#include <cuda_bf16.h>

// Problem constants (fixed by reference setup_inputs):
//   b=4, u=9, v=9 (MD=4, FAC=1), h=256, w=448, WSIZE=3
#define MD    4
#define V_DIM 9
#define UV    81
#define WS    3
#define B_DIM 4
#define HW_FIXED 114688   // 256*448

// ln2 / log(49), ln2 / log(81): convert log2-domain (logZ - S/Z) to normalized nats
#define C49 ((float)(0.6931471805599453 / 3.8918202981106265))
#define C81 ((float)(0.6931471805599453 / 4.3944491546724391))
#define L2E 1.4426950408889634f

__device__ __forceinline__ float ex2(float a) {
    float r;
    asm("ex2.approx.f32 %0, %1;" : "=f"(r) : "f"(a));
    return r;
}
__device__ __forceinline__ float lg2(float a) {
    float r;
    asm("lg2.approx.f32 %0, %1;" : "=f"(r) : "f"(a));
    return r;
}

template<int HW_CT>
__global__ __launch_bounds__(256) void flow_reg_kernel(
    const float* __restrict__ x,   // (B, U, V, H, W)
    float* __restrict__ out,       // flow (B,2,H,W) then ent (B,2,H,W)
    int hw_rt, int bhw)
{
    const int hw = (HW_CT > 0) ? HW_CT : hw_rt;

    int t = blockIdx.x * blockDim.x + threadIdx.x;
    if (t >= bhw) return;
    int b = t / hw;
    int p = t - b * hw;

    const float* xp = x + (size_t)b * UV * hw + p;

    // ---- load 81-deep column, pre-scaled to log2 domain (compile-time offsets) ----
    float xs[UV];
#pragma unroll
    for (int k = 0; k < UV; ++k)
        xs[k] = __ldg(xp + (size_t)k * hw) * L2E;

    // ---- argmax (first occurrence; positive scale preserves argmax) ----
    float ms = xs[0];
    int am = 0;
#pragma unroll
    for (int k = 1; k < UV; ++k)
        if (xs[k] > ms) { ms = xs[k]; am = k; }
    int iu = am / V_DIM;
    int iv = am - iu * V_DIM;

    // ---- 0/1 float mask coefficients: column (v) and row (u) ----
    float bcf[V_DIM], ru[V_DIM];
#pragma unroll
    for (int v = 0; v < V_DIM; ++v)
        bcf[v] = ((unsigned)(v - iv + WS) <= 2u * WS) ? 1.0f : 0.0f;
#pragma unroll
    for (int u = 0; u < V_DIM; ++u)
        ru[u] = ((unsigned)(u - iu + WS) <= 2u * WS) ? 1.0f : 0.0f;

    // ---- fused pass, row-factored masked accumulation (all in log2 domain) ----
    float Z = 0.f, S = 0.f, Zl = 0.f, Sl = 0.f, Fx = 0.f, Fy = 0.f;
#pragma unroll
    for (int u = 0; u < V_DIM; ++u) {
        float rZ = 0.f, rS = 0.f, rFy = 0.f;
#pragma unroll
        for (int v = 0; v < V_DIM; ++v) {
            const int k = u * V_DIM + v;
            float d = xs[k] - ms;          // log2-domain delta, <= 0
            float e = ex2(d);              // == exp(x - m)
            Z += e;
            S = fmaf(d, e, S);
            float emc = e * bcf[v];        // column-masked
            rZ  += emc;
            rS   = fmaf(d, emc, rS);
            rFy  = fmaf((float)(v - MD), emc, rFy);
        }
        float tm = ru[u] * rZ;             // row-masked
        Zl += tm;
        Fx  = fmaf((float)(u - MD), tm, Fx);
        Sl  = fmaf(ru[u], rS, Sl);
        Fy  = fmaf(ru[u], rFy, Fy);
    }

    float rZl = 1.0f / Zl;
    float rZg = 1.0f / Z;
    float outx = Fx * rZl;
    float outy = Fy * rZl;
    // entropy(nats) = ln Z - S_nat/Z ; here logs/deltas are base-2, so multiply by ln2
    float lent = (lg2(Zl) - Sl * rZl) * C49;
    float gent = (lg2(Z)  - S  * rZg) * C81;

    // ---- write: flow block (B,2,H,W) then ent block (B,2,H,W) ----
    float* fo = out + (size_t)b * 2 * hw + p;
    fo[0]  = outx;
    fo[hw] = outy;
    float* eo = fo + (size_t)B_DIM * 2 * hw;
    eo[0]  = lent;
    eo[hw] = gent;
}

extern "C" void kernel_launch(void* const* d_in, const int* in_sizes, int n_in,
                              void* d_out, int out_size)
{
    const float* x = (const float*)d_in[0];
    float* out = (float*)d_out;

    int hw  = in_sizes[0] / (UV * B_DIM);
    int bhw = B_DIM * hw;

    int threads = 256;
    int blocks = (bhw + threads - 1) / threads;
    if (hw == HW_FIXED)
        flow_reg_kernel<HW_FIXED><<<blocks, threads>>>(x, out, hw, bhw);
    else
        flow_reg_kernel<0><<<blocks, threads>>>(x, out, hw, bhw);
}

// round 5
// speedup vs baseline: 1.0991x; 1.0062x over previous
#include <cuda_runtime.h>
#include <cuda_bf16.h>

// Fixed problem shape: b=4, u=9, v=9 (MD=4), h=256, w=448, WSIZE=3
#define MD    4
#define V_DIM 9
#define UV    81
#define WS    3
#define B_DIM 4
#define HW_FIXED 114688

// ln2 / log(49), ln2 / log(81): convert base-2 (logZ - S/Z) to normalized nats
#define C49 ((float)(0.6931471805599453 / 3.8918202981106265))
#define C81 ((float)(0.6931471805599453 / 4.3944491546724391))
#define L2E 1.4426950408889634f
#define XPAD (-1e30f)

typedef unsigned long long u64;

__device__ __forceinline__ float ex2(float a) {
    float r; asm("ex2.approx.f32 %0, %1;" : "=f"(r) : "f"(a)); return r;
}
__device__ __forceinline__ float lg2(float a) {
    float r; asm("lg2.approx.f32 %0, %1;" : "=f"(r) : "f"(a)); return r;
}
__device__ __forceinline__ u64 pk(float lo, float hi) {
    u64 r; asm("mov.b64 %0, {%1, %2};" : "=l"(r) : "f"(lo), "f"(hi)); return r;
}
__device__ __forceinline__ void unpk(float& lo, float& hi, u64 a) {
    asm("mov.b64 {%0, %1}, %2;" : "=f"(lo), "=f"(hi) : "l"(a));
}
__device__ __forceinline__ u64 fma2(u64 a, u64 b, u64 c) {
    u64 r; asm("fma.rn.f32x2 %0, %1, %2, %3;" : "=l"(r) : "l"(a), "l"(b), "l"(c)); return r;
}
__device__ __forceinline__ u64 add2(u64 a, u64 b) {
    u64 r; asm("add.rn.f32x2 %0, %1, %2;" : "=l"(r) : "l"(a), "l"(b)); return r;
}
__device__ __forceinline__ u64 mul2(u64 a, u64 b) {
    u64 r; asm("mul.rn.f32x2 %0, %1, %2;" : "=l"(r) : "l"(a), "l"(b)); return r;
}

// packed (v-4) coefficient pairs for v = (0,1),(2,3),(4,5),(6,7),(8,pad0)
__device__ __constant__ u64 CV2[5] = {
    0xC0400000C0800000ULL, 0xBF800000C0000000ULL, 0x3F80000000000000ULL,
    0x4040000040000000ULL, 0x0000000040800000ULL
};
// packed broadcast (u-4) per row u=0..8
__device__ __constant__ u64 CU2[9] = {
    0xC0800000C0800000ULL, 0xC0400000C0400000ULL, 0xC0000000C0000000ULL,
    0xBF800000BF800000ULL, 0x0000000000000000ULL, 0x3F8000003F800000ULL,
    0x4000000040000000ULL, 0x4040000040400000ULL, 0x4080000040800000ULL
};

template<int HW_CT>
__global__ __launch_bounds__(128) void flow_reg_kernel(
    const float* __restrict__ x,   // (B, U, V, H, W)
    float* __restrict__ out,       // flow (B,2,H,W) then ent (B,2,H,W)
    int hw_rt, int bhw)
{
    const int hw = (HW_CT > 0) ? HW_CT : hw_rt;

    int t = blockIdx.x * blockDim.x + threadIdx.x;
    if (t >= bhw) return;
    int b = t / hw;
    int p = t - b * hw;

    const float* xp = x + (size_t)b * UV * hw + p;

    // ---- load 81-deep column (raw), coalesced per plane, compile-time offsets ----
    float xv[UV];
#pragma unroll
    for (int k = 0; k < UV; ++k)
        xv[k] = __ldg(xp + (size_t)k * hw);

    // ---- argmax (first occurrence, matches jnp.argmax) ----
    float m = xv[0];
    int am = 0;
#pragma unroll
    for (int k = 1; k < UV; ++k)
        if (xv[k] > m) { m = xv[k]; am = k; }
    int iu = am / V_DIM;
    int iv = am - iu * V_DIM;

    // ---- packed column-mask pairs B2[j] (0/1 floats), pad col -> 0 ----
    u64 B2[5];
#pragma unroll
    for (int j = 0; j < 5; ++j) {
        int v0 = 2 * j, v1 = 2 * j + 1;
        float c0 = ((unsigned)(v0 - iv + WS) <= 2u * WS) ? 1.0f : 0.0f;
        float c1 = (v1 < V_DIM && (unsigned)(v1 - iv + WS) <= 2u * WS) ? 1.0f : 0.0f;
        B2[j] = pk(c0, c1);
    }

    const float msc = m * L2E;
    const u64 NM2  = pk(-msc, -msc);
    const u64 L2E2 = pk(L2E, L2E);

    // ---- fused accumulation, fully packed f32x2 ----
    u64 Z2 = 0, S2 = 0, ZL2 = 0, SL2 = 0, FX2 = 0, FY2 = 0;
#pragma unroll
    for (int u = 0; u < V_DIM; ++u) {
        float ruf = ((unsigned)(u - iu + WS) <= 2u * WS) ? 1.0f : 0.0f;
        u64 RU2 = pk(ruf, ruf);
        u64 W0 = mul2(RU2, B2[0]);
        u64 W1 = mul2(RU2, B2[1]);
        u64 W2w = mul2(RU2, B2[2]);
        u64 W3 = mul2(RU2, B2[3]);
        u64 W4 = mul2(RU2, B2[4]);
        const u64 cu2 = CU2[u];
#pragma unroll
        for (int j = 0; j < 5; ++j) {
            const int k = u * V_DIM + 2 * j;
            float x0 = xv[k];
            float x1 = (2 * j + 1 < V_DIM) ? xv[k + 1] : XPAD;
            u64 X2 = pk(x0, x1);
            u64 D2 = fma2(X2, L2E2, NM2);           // log2-domain deltas (pad: finite huge-neg)
            float d0, d1; unpk(d0, d1, D2);
            u64 E2 = pk(ex2(d0), ex2(d1));          // exp(x - m); pad -> +0
            Z2 = add2(Z2, E2);
            S2 = fma2(D2, E2, S2);
            u64 W = (j == 0) ? W0 : (j == 1) ? W1 : (j == 2) ? W2w : (j == 3) ? W3 : W4;
            u64 EW2 = mul2(E2, W);                  // masked e
            ZL2 = add2(ZL2, EW2);
            SL2 = fma2(D2, EW2, SL2);
            FY2 = fma2(CV2[j], EW2, FY2);
            FX2 = fma2(cu2, EW2, FX2);
        }
    }

    float a0, a1;
    unpk(a0, a1, Z2);  float Z  = a0 + a1;
    unpk(a0, a1, S2);  float S  = a0 + a1;
    unpk(a0, a1, ZL2); float Zl = a0 + a1;
    unpk(a0, a1, SL2); float Sl = a0 + a1;
    unpk(a0, a1, FX2); float Fx = a0 + a1;
    unpk(a0, a1, FY2); float Fy = a0 + a1;

    float rZl = 1.0f / Zl;
    float rZg = 1.0f / Z;
    float outx = Fx * rZl;
    float outy = Fy * rZl;
    float lent = (lg2(Zl) - Sl * rZl) * C49;
    float gent = (lg2(Z)  - S  * rZg) * C81;

    float* fo = out + (size_t)b * 2 * hw + p;
    fo[0]  = outx;
    fo[hw] = outy;
    float* eo = fo + (size_t)B_DIM * 2 * hw;
    eo[0]  = lent;
    eo[hw] = gent;
}

extern "C" void kernel_launch(void* const* d_in, const int* in_sizes, int n_in,
                              void* d_out, int out_size)
{
    const float* x = (const float*)d_in[0];
    float* out = (float*)d_out;

    int hw  = in_sizes[0] / (UV * B_DIM);
    int bhw = B_DIM * hw;

    int threads = 128;
    int blocks = (bhw + threads - 1) / threads;
    if (hw == HW_FIXED)
        flow_reg_kernel<HW_FIXED><<<blocks, threads>>>(x, out, hw, bhw);
    else
        flow_reg_kernel<0><<<blocks, threads>>>(x, out, hw, bhw);
}